// round 11
// baseline (speedup 1.0000x reference)
#include <cuda_runtime.h>
#include <cuda_bf16.h>

#define Hh 100
#define Ww 136
#define HW (Hh*Ww)      // 13600
#define OH 200
#define OW 272
#define OHW (OH*OW)     // 54400
#define NPARAM 169

typedef unsigned long long u64;

// ---- packed f32x2 helpers ----
__device__ __forceinline__ u64 pack2(float a, float b) {
    u64 r; asm("mov.b64 %0, {%1, %2};" : "=l"(r) : "f"(a), "f"(b)); return r;
}
__device__ __forceinline__ void unpack2(u64 v, float& a, float& b) {
    asm("mov.b64 {%0, %1}, %2;" : "=f"(a), "=f"(b) : "l"(v));
}
__device__ __forceinline__ u64 fma2(u64 a, u64 b, u64 c) {
    u64 d; asm("fma.rn.f32x2 %0, %1, %2, %3;" : "=l"(d) : "l"(a), "l"(b), "l"(c)); return d;
}
__device__ __forceinline__ u64 relu2(u64 v) {
    float a, b; unpack2(v, a, b);
    return pack2(fmaxf(a, 0.f), fmaxf(b, 0.f));
}
__device__ __forceinline__ float sigm(float z) {
    float t; asm("tanh.approx.f32 %0, %1;" : "=f"(t) : "f"(z * 0.5f));
    return fmaf(t, 0.5f, 0.5f);
}

// params layout: w0[8][10]@0, w1[8][8]@80, w2[8]@144, b0[8]@152, b1[8]@160, b2@168

__global__ void dmh_zero(float* out) { out[0] = 0.0f; }

__global__ void __launch_bounds__(256)      // no CTA/reg cap: ILP > occupancy here
dmh_kernel(const float* __restrict__ mask_feats,
           const float* __restrict__ params,
           const float* __restrict__ locs,
           const float* __restrict__ gt,
           const int*   __restrict__ im_inds,
           const int*   __restrict__ fpn_levels,
           float* __restrict__ out,
           float inv_n)
{
    extern __shared__ float smem[];
    float* Ls  = smem;                          // HW logits
    u64*   Wd  = (u64*)(smem + HW);             // 170 duplicated params (16B-aligned)
    float* red = (float*)(Wd + NPARAM + 1);     // 24 floats reduction scratch

    const int inst = blockIdx.x;
    const int tid  = threadIdx.x;

    // ---- Phase A: load per-instance params, duplicated for packed math ----
    for (int i = tid; i < NPARAM; i += blockDim.x) {
        float w = params[inst * NPARAM + i];
        Wd[i] = pack2(w, w);
    }
    if (tid == 0) Wd[NPARAM] = 0;   // pad so ull2 read of pair (168,169) is safe

    const int im  = im_inds[inst];
    const int lvl = fpn_levels[inst];
    const float soi_tab[5] = {8.f, 16.f, 32.f, 64.f, 128.f};
    const float inv_soi = 1.0f / soi_tab[lvl];
    const float lx = locs[inst * 2 + 0];
    const float ly = locs[inst * 2 + 1];
    const float* __restrict__ feat = mask_feats + (size_t)im * 8 * HW;
    __syncthreads();

    const ulonglong2* __restrict__ W2 = (const ulonglong2*)Wd;   // 16B-aligned

    // ---- Phase B: per-pixel 3-layer MLP, 4 px/thread, LDS.128 weights ----
    for (int p0 = tid * 4; p0 < HW; p0 += blockDim.x * 4) {
        int y = p0 / Ww;
        int x = p0 - y * Ww;
        float cy  = (ly - (float)(y * 8 + 4)) * inv_soi;
        float cx0 = (lx - (float)(x * 8 + 4)) * inv_soi;
        float dx  = -8.f * inv_soi;

        u64 v2[10][2];
        v2[0][0] = pack2(cx0, cx0 + dx);
        v2[0][1] = pack2(cx0 + 2.f * dx, cx0 + 3.f * dx);
        v2[1][0] = pack2(cy, cy);
        v2[1][1] = v2[1][0];
        #pragma unroll
        for (int c = 0; c < 8; c++) {
            float4 f = *reinterpret_cast<const float4*>(feat + c * HW + p0);
            v2[2 + c][0] = pack2(f.x, f.y);
            v2[2 + c][1] = pack2(f.z, f.w);
        }

        u64 h0[8][2];
        #pragma unroll
        for (int c = 0; c < 8; c++) {
            u64 b  = Wd[152 + c];
            u64 a0 = b, a1 = b;
            #pragma unroll
            for (int i2 = 0; i2 < 5; i2++) {        // w0 row c: 5 x LDS.128
                ulonglong2 wp = W2[c * 5 + i2];
                a0 = fma2(wp.x, v2[2*i2][0],   a0);
                a1 = fma2(wp.x, v2[2*i2][1],   a1);
                a0 = fma2(wp.y, v2[2*i2+1][0], a0);
                a1 = fma2(wp.y, v2[2*i2+1][1], a1);
            }
            h0[c][0] = relu2(a0);
            h0[c][1] = relu2(a1);
        }

        u64 h1[8][2];
        #pragma unroll
        for (int c = 0; c < 8; c++) {
            u64 b  = Wd[160 + c];
            u64 a0 = b, a1 = b;
            #pragma unroll
            for (int i2 = 0; i2 < 4; i2++) {        // w1 row c: 4 x LDS.128
                ulonglong2 wp = W2[40 + c * 4 + i2];
                a0 = fma2(wp.x, h0[2*i2][0],   a0);
                a1 = fma2(wp.x, h0[2*i2][1],   a1);
                a0 = fma2(wp.y, h0[2*i2+1][0], a0);
                a1 = fma2(wp.y, h0[2*i2+1][1], a1);
            }
            h1[c][0] = relu2(a0);
            h1[c][1] = relu2(a1);
        }

        u64 zb = Wd[168];
        u64 z0 = zb, z1 = zb;
        #pragma unroll
        for (int i2 = 0; i2 < 4; i2++) {            // w2: 4 x LDS.128
            ulonglong2 wp = W2[72 + i2];
            z0 = fma2(wp.x, h1[2*i2][0],   z0);
            z1 = fma2(wp.x, h1[2*i2][1],   z1);
            z0 = fma2(wp.y, h1[2*i2+1][0], z0);
            z1 = fma2(wp.y, h1[2*i2+1][1], z1);
        }
        float o0, o1, o2, o3;
        unpack2(z0, o0, o1);
        unpack2(z1, o2, o3);
        *reinterpret_cast<float4*>(Ls + p0) = make_float4(o0, o1, o2, o3);
    }
    __syncthreads();

    // ---- Phase C: 32 px/thread/iter, 8 front-batched LDG.128 (MLP=8) ----
    float inter = 0.f, ssum = 0.f, tsum = 0.f;
    const float* __restrict__ g = gt + (size_t)inst * OHW;
    const int NCHUNK = OHW / 16;   // 3400 (even), OW = 17*16

    for (int ch = tid * 2; ch < NCHUNK; ch += blockDim.x * 2) {
        int chB = ch + 1;          // always < NCHUNK (ch even, NCHUNK even)

        int yA  = ch / 17;
        int xA  = (ch - yA * 17) * 16;
        int qA  = yA * OW + xA;
        int yB  = chB / 17;
        int xB  = (chB - yB * 17) * 16;
        int qB  = yB * OW + xB;

        // 8 independent global loads, front-batched
        float4 tA0 = *reinterpret_cast<const float4*>(g + qA);
        float4 tA1 = *reinterpret_cast<const float4*>(g + qA + 4);
        float4 tA2 = *reinterpret_cast<const float4*>(g + qA + 8);
        float4 tA3 = *reinterpret_cast<const float4*>(g + qA + 12);
        float4 tB0 = *reinterpret_cast<const float4*>(g + qB);
        float4 tB1 = *reinterpret_cast<const float4*>(g + qB + 4);
        float4 tB2 = *reinterpret_cast<const float4*>(g + qB + 8);
        float4 tB3 = *reinterpret_cast<const float4*>(g + qB + 12);

        #pragma unroll
        for (int half = 0; half < 2; half++) {
            int y  = half ? yB : yA;
            int xc = half ? xB : xA;
            float4 t0 = half ? tB0 : tA0;
            float4 t1 = half ? tB1 : tA1;
            float4 t2 = half ? tB2 : tA2;
            float4 t3 = half ? tB3 : tA3;

            int jy  = max(y - 1, 0);
            int iy0 = jy >> 1;
            int iy1 = iy0 + (jy & 1);
            const float* r0 = Ls + iy0 * Ww;
            const float* r1 = Ls + iy1 * Ww;

            int c0 = xc >> 1;               // multiple of 8 -> 16B aligned
            int cm = max(c0 - 1, 0);

            float4 A0 = *reinterpret_cast<const float4*>(r0 + c0);
            float4 B0 = *reinterpret_cast<const float4*>(r0 + c0 + 4);
            float4 A1 = *reinterpret_cast<const float4*>(r1 + c0);
            float4 B1 = *reinterpret_cast<const float4*>(r1 + c0 + 4);
            float  m0 = r0[cm];
            float  m1 = r1[cm];

            float Em = 0.5f * (m0 + m1);
            float E[8];
            E[0] = 0.5f * (A0.x + A1.x);
            E[1] = 0.5f * (A0.y + A1.y);
            E[2] = 0.5f * (A0.z + A1.z);
            E[3] = 0.5f * (A0.w + A1.w);
            E[4] = 0.5f * (B0.x + B1.x);
            E[5] = 0.5f * (B0.y + B1.y);
            E[6] = 0.5f * (B0.z + B1.z);
            E[7] = 0.5f * (B0.w + B1.w);

            float gtv[16] = {t0.x, t0.y, t0.z, t0.w, t1.x, t1.y, t1.z, t1.w,
                             t2.x, t2.y, t2.z, t2.w, t3.x, t3.y, t3.z, t3.w};
            #pragma unroll
            for (int j = 0; j < 4; j++) {
                float ep = (j == 0) ? Em : E[2 * j - 1];
                float e0 = E[2 * j];
                float e1 = E[2 * j + 1];
                float s0 = sigm(0.5f * (ep + e0));
                float s1 = sigm(e0);
                float s2 = sigm(0.5f * (e0 + e1));
                float s3 = sigm(e1);
                float g0 = gtv[4 * j + 0], g1 = gtv[4 * j + 1];
                float g2 = gtv[4 * j + 2], g3 = gtv[4 * j + 3];
                inter = fmaf(s0, g0, inter); ssum = fmaf(s0, s0, ssum); tsum = fmaf(g0, g0, tsum);
                inter = fmaf(s1, g1, inter); ssum = fmaf(s1, s1, ssum); tsum = fmaf(g1, g1, tsum);
                inter = fmaf(s2, g2, inter); ssum = fmaf(s2, s2, ssum); tsum = fmaf(g2, g2, tsum);
                inter = fmaf(s3, g3, inter); ssum = fmaf(s3, s3, ssum); tsum = fmaf(g3, g3, tsum);
            }
        }
    }

    // ---- Phase D: block reduce, per-instance dice, atomic mean ----
    #pragma unroll
    for (int off = 16; off > 0; off >>= 1) {
        inter += __shfl_down_sync(0xffffffffu, inter, off);
        ssum  += __shfl_down_sync(0xffffffffu, ssum,  off);
        tsum  += __shfl_down_sync(0xffffffffu, tsum,  off);
    }
    int warp = tid >> 5;
    if ((tid & 31) == 0) {
        red[warp]      = inter;
        red[8 + warp]  = ssum;
        red[16 + warp] = tsum;
    }
    __syncthreads();
    if (tid == 0) {
        float I = 0.f, S = 0.f, T = 0.f;
        #pragma unroll
        for (int w = 0; w < 8; w++) { I += red[w]; S += red[8 + w]; T += red[16 + w]; }
        float loss = 1.0f - 2.0f * I / (S + T + 1e-5f);
        atomicAdd(out, loss * inv_n);
    }
}

extern "C" void kernel_launch(void* const* d_in, const int* in_sizes, int n_in,
                              void* d_out, int out_size)
{
    const float* mask_feats = (const float*)d_in[0];
    const float* params     = (const float*)d_in[1];
    const float* locs       = (const float*)d_in[2];
    const float* gt         = (const float*)d_in[3];
    const int*   im_inds    = (const int*)d_in[4];
    const int*   fpn_levels = (const int*)d_in[5];
    float* out = (float*)d_out;

    int n_inst = in_sizes[1] / NPARAM;

    static int smem_set = 0;
    size_t smem_bytes = HW * sizeof(float) + (NPARAM + 1) * sizeof(u64) + 32 * sizeof(float);
    if (!smem_set) {
        cudaFuncSetAttribute(dmh_kernel, cudaFuncAttributeMaxDynamicSharedMemorySize,
                             (int)smem_bytes);
        smem_set = 1;
    }

    dmh_zero<<<1, 1>>>(out);
    dmh_kernel<<<n_inst, 256, smem_bytes>>>(mask_feats, params, locs, gt,
                                            im_inds, fpn_levels, out,
                                            1.0f / (float)n_inst);
}

// round 14
// speedup vs baseline: 1.0403x; 1.0403x over previous
#include <cuda_runtime.h>
#include <cuda_bf16.h>

#define Hh 100
#define Ww 136
#define HW (Hh*Ww)      // 13600
#define OH 200
#define OW 272
#define OHW (OH*OW)     // 54400
#define NPARAM 169
#define MAXINST 512

typedef unsigned long long u64;

__device__ float g_logits[MAXINST * HW];   // 27.8 MB logit scratch (L2-resident)
__device__ float g_part[MAXINST * 3];      // per-instance (inter, ssum, tsum)

// ---- packed f32x2 helpers ----
__device__ __forceinline__ u64 pack2(float a, float b) {
    u64 r; asm("mov.b64 %0, {%1, %2};" : "=l"(r) : "f"(a), "f"(b)); return r;
}
__device__ __forceinline__ void unpack2(u64 v, float& a, float& b) {
    asm("mov.b64 {%0, %1}, %2;" : "=f"(a), "=f"(b) : "l"(v));
}
__device__ __forceinline__ u64 fma2(u64 a, u64 b, u64 c) {
    u64 d; asm("fma.rn.f32x2 %0, %1, %2, %3;" : "=l"(d) : "l"(a), "l"(b), "l"(c)); return d;
}
__device__ __forceinline__ u64 relu2(u64 v) {
    float a, b; unpack2(v, a, b);
    return pack2(fmaxf(a, 0.f), fmaxf(b, 0.f));
}
__device__ __forceinline__ float sigm(float z) {
    float t; asm("tanh.approx.f32 %0, %1;" : "=f"(t) : "f"(z * 0.5f));
    return fmaf(t, 0.5f, 0.5f);
}

// params layout: w0[8][10]@0, w1[8][8]@80, w2[8]@144, b0[8]@152, b1[8]@160, b2@168

__global__ void dmh_zero() {
    for (int i = threadIdx.x; i < MAXINST * 3; i += blockDim.x)
        g_part[i] = 0.0f;
}

// ===== K1: per-pixel MLP, all weights channel-pair-packed in REGISTERS =====
// grid = 2*n_inst, block = 128. Block b: instance b>>1, pixel half b&1.
__global__ void __launch_bounds__(128, 2)
k_mlp(const float* __restrict__ mask_feats,
      const float* __restrict__ params,
      const float* __restrict__ locs,
      const int*   __restrict__ im_inds,
      const int*   __restrict__ fpn_levels)
{
    const int inst = blockIdx.x >> 1;
    const int half = blockIdx.x & 1;
    const int tid  = threadIdx.x;

    const float* __restrict__ P = params + inst * NPARAM;

    // ---- load all weights into registers, packed by channel pair ----
    u64 w0p[4][10], w1p[4][8], w2p[4], b0p[4], b1p[4];
    #pragma unroll
    for (int c2 = 0; c2 < 4; c2++) {
        #pragma unroll
        for (int i = 0; i < 10; i++)
            w0p[c2][i] = pack2(__ldg(P + (2*c2)*10 + i), __ldg(P + (2*c2+1)*10 + i));
        #pragma unroll
        for (int i = 0; i < 8; i++)
            w1p[c2][i] = pack2(__ldg(P + 80 + (2*c2)*8 + i), __ldg(P + 80 + (2*c2+1)*8 + i));
        w2p[c2] = pack2(__ldg(P + 144 + 2*c2), __ldg(P + 144 + 2*c2 + 1));
        b0p[c2] = pack2(__ldg(P + 152 + 2*c2), __ldg(P + 152 + 2*c2 + 1));
        b1p[c2] = pack2(__ldg(P + 160 + 2*c2), __ldg(P + 160 + 2*c2 + 1));
    }
    const float b2 = __ldg(P + 168);

    const int im  = im_inds[inst];
    const int lvl = fpn_levels[inst];
    const float soi_tab[5] = {8.f, 16.f, 32.f, 64.f, 128.f};
    const float inv_soi = 1.0f / soi_tab[lvl];
    const float lx = locs[inst * 2 + 0];
    const float ly = locs[inst * 2 + 1];
    const float* __restrict__ feat = mask_feats + (size_t)im * 8 * HW;
    float* __restrict__ Lout = g_logits + (size_t)inst * HW;

    const int p_lo = half * (HW / 2);            // 6800 px per half (50 rows)
    const int p_hi = p_lo + HW / 2;

    for (int p = p_lo + tid; p < p_hi; p += 128) {
        int y = p / Ww;
        int x = p - y * Ww;
        float vx = (lx - (float)(x * 8 + 4)) * inv_soi;
        float vy = (ly - (float)(y * 8 + 4)) * inv_soi;

        u64 vd[10];
        vd[0] = pack2(vx, vx);
        vd[1] = pack2(vy, vy);
        #pragma unroll
        for (int c = 0; c < 8; c++) {
            float f = __ldg(feat + c * HW + p);
            vd[2 + c] = pack2(f, f);
        }

        // layer 1: 4 channel-pairs, weights in regs
        u64 h0p[4];
        #pragma unroll
        for (int c2 = 0; c2 < 4; c2++) {
            u64 a = b0p[c2];
            #pragma unroll
            for (int i = 0; i < 10; i++)
                a = fma2(w0p[c2][i], vd[i], a);
            h0p[c2] = relu2(a);
        }

        // duplicate h0 scalars for layer 2
        u64 hd[8];
        #pragma unroll
        for (int c2 = 0; c2 < 4; c2++) {
            float a, b; unpack2(h0p[c2], a, b);
            hd[2*c2]     = pack2(a, a);
            hd[2*c2 + 1] = pack2(b, b);
        }

        // layer 2
        u64 h1p[4];
        #pragma unroll
        for (int c2 = 0; c2 < 4; c2++) {
            u64 a = b1p[c2];
            #pragma unroll
            for (int i = 0; i < 8; i++)
                a = fma2(w1p[c2][i], hd[i], a);
            h1p[c2] = relu2(a);
        }

        // layer 3: pairwise dot, horizontal add
        u64 zp = pack2(b2, 0.0f);
        #pragma unroll
        for (int i2 = 0; i2 < 4; i2++)
            zp = fma2(w2p[i2], h1p[i2], zp);
        float za, zb; unpack2(zp, za, zb);
        Lout[p] = za + zb;
    }
}

// ===== K2: aligned_bilinear(x2) + sigmoid + dice partials =====
// grid = 2*n_inst, block = 256. Logits read from g_logits (L2-hot).
__global__ void __launch_bounds__(256)
k_dice(const float* __restrict__ gt)
{
    __shared__ float red[24];
    const int inst = blockIdx.x >> 1;
    const int half = blockIdx.x & 1;
    const int tid  = threadIdx.x;

    const float* __restrict__ g = gt + (size_t)inst * OHW;
    const float* __restrict__ L = g_logits + (size_t)inst * HW;

    float inter = 0.f, ssum = 0.f, tsum = 0.f;
    const int ch_lo = half * (OHW / 32);         // 1700 chunks of 16 px per half
    const int ch_hi = ch_lo + OHW / 32;

    for (int ch = ch_lo + tid; ch < ch_hi; ch += 256) {
        int y  = ch / 17;
        int xc = (ch - y * 17) * 16;
        int q0 = y * OW + xc;

        // 4 independent gt loads (DRAM stream)
        float4 t0 = *reinterpret_cast<const float4*>(g + q0);
        float4 t1 = *reinterpret_cast<const float4*>(g + q0 + 4);
        float4 t2 = *reinterpret_cast<const float4*>(g + q0 + 8);
        float4 t3 = *reinterpret_cast<const float4*>(g + q0 + 12);

        int jy  = max(y - 1, 0);
        int iy0 = jy >> 1;
        int iy1 = iy0 + (jy & 1);
        const float* __restrict__ r0 = L + iy0 * Ww;
        const float* __restrict__ r1 = L + iy1 * Ww;

        int c0 = xc >> 1;                        // multiple of 8 -> 16B aligned
        int cm = max(c0 - 1, 0);

        // logit loads (L2/L1 hits)
        float4 A0 = *reinterpret_cast<const float4*>(r0 + c0);
        float4 B0 = *reinterpret_cast<const float4*>(r0 + c0 + 4);
        float4 A1 = *reinterpret_cast<const float4*>(r1 + c0);
        float4 B1 = *reinterpret_cast<const float4*>(r1 + c0 + 4);
        float  m0 = __ldg(r0 + cm);
        float  m1 = __ldg(r1 + cm);

        float Em = 0.5f * (m0 + m1);
        float E[8];
        E[0] = 0.5f * (A0.x + A1.x);
        E[1] = 0.5f * (A0.y + A1.y);
        E[2] = 0.5f * (A0.z + A1.z);
        E[3] = 0.5f * (A0.w + A1.w);
        E[4] = 0.5f * (B0.x + B1.x);
        E[5] = 0.5f * (B0.y + B1.y);
        E[6] = 0.5f * (B0.z + B1.z);
        E[7] = 0.5f * (B0.w + B1.w);

        float gtv[16] = {t0.x, t0.y, t0.z, t0.w, t1.x, t1.y, t1.z, t1.w,
                         t2.x, t2.y, t2.z, t2.w, t3.x, t3.y, t3.z, t3.w};
        #pragma unroll
        for (int j = 0; j < 4; j++) {
            float ep = (j == 0) ? Em : E[2 * j - 1];
            float e0 = E[2 * j];
            float e1 = E[2 * j + 1];
            float s0 = sigm(0.5f * (ep + e0));
            float s1 = sigm(e0);
            float s2 = sigm(0.5f * (e0 + e1));
            float s3 = sigm(e1);
            float g0 = gtv[4 * j + 0], g1 = gtv[4 * j + 1];
            float g2 = gtv[4 * j + 2], g3 = gtv[4 * j + 3];
            inter = fmaf(s0, g0, inter); ssum = fmaf(s0, s0, ssum); tsum = fmaf(g0, g0, tsum);
            inter = fmaf(s1, g1, inter); ssum = fmaf(s1, s1, ssum); tsum = fmaf(g1, g1, tsum);
            inter = fmaf(s2, g2, inter); ssum = fmaf(s2, s2, ssum); tsum = fmaf(g2, g2, tsum);
            inter = fmaf(s3, g3, inter); ssum = fmaf(s3, s3, ssum); tsum = fmaf(g3, g3, tsum);
        }
    }

    // block reduce, accumulate per-instance partials
    #pragma unroll
    for (int off = 16; off > 0; off >>= 1) {
        inter += __shfl_down_sync(0xffffffffu, inter, off);
        ssum  += __shfl_down_sync(0xffffffffu, ssum,  off);
        tsum  += __shfl_down_sync(0xffffffffu, tsum,  off);
    }
    int warp = tid >> 5;
    if ((tid & 31) == 0) {
        red[warp]      = inter;
        red[8 + warp]  = ssum;
        red[16 + warp] = tsum;
    }
    __syncthreads();
    if (tid == 0) {
        float I = 0.f, S = 0.f, T = 0.f;
        #pragma unroll
        for (int w = 0; w < 8; w++) { I += red[w]; S += red[8 + w]; T += red[16 + w]; }
        atomicAdd(&g_part[inst * 3 + 0], I);
        atomicAdd(&g_part[inst * 3 + 1], S);
        atomicAdd(&g_part[inst * 3 + 2], T);
    }
}

// ===== K3: per-instance dice ratio + mean =====
__global__ void dmh_final(float* __restrict__ out, int n_inst, float inv_n) {
    __shared__ float sred[16];
    int tid = threadIdx.x;
    float l = 0.f;
    if (tid < n_inst) {
        float I = g_part[tid * 3 + 0];
        float S = g_part[tid * 3 + 1];
        float T = g_part[tid * 3 + 2];
        l = 1.0f - 2.0f * I / (S + T + 1e-5f);
    }
    #pragma unroll
    for (int off = 16; off > 0; off >>= 1)
        l += __shfl_down_sync(0xffffffffu, l, off);
    if ((tid & 31) == 0) sred[tid >> 5] = l;
    __syncthreads();
    if (tid == 0) {
        float s = 0.f;
        #pragma unroll
        for (int w = 0; w < 16; w++) s += sred[w];
        out[0] = s * inv_n;
    }
}

extern "C" void kernel_launch(void* const* d_in, const int* in_sizes, int n_in,
                              void* d_out, int out_size)
{
    const float* mask_feats = (const float*)d_in[0];
    const float* params     = (const float*)d_in[1];
    const float* locs       = (const float*)d_in[2];
    const float* gt         = (const float*)d_in[3];
    const int*   im_inds    = (const int*)d_in[4];
    const int*   fpn_levels = (const int*)d_in[5];
    float* out = (float*)d_out;

    int n_inst = in_sizes[1] / NPARAM;

    dmh_zero<<<1, 512>>>();
    k_mlp<<<2 * n_inst, 128>>>(mask_feats, params, locs, im_inds, fpn_levels);
    k_dice<<<2 * n_inst, 256>>>(gt);
    dmh_final<<<1, 512>>>(out, n_inst, 1.0f / (float)n_inst);
}

// round 15
// speedup vs baseline: 1.2153x; 1.1683x over previous
#include <cuda_runtime.h>
#include <cuda_bf16.h>

#define Hh 100
#define Ww 136
#define HW (Hh*Ww)      // 13600
#define OH 200
#define OW 272
#define OHW (OH*OW)     // 54400
#define NPARAM 169
#define GT_LINES 1700   // 217600 B per instance / 128 B

typedef unsigned long long u64;

__device__ float        g_sum   = 0.0f;   // cross-CTA loss accumulator
__device__ unsigned int g_count = 0u;     // completion counter

// ---- packed f32x2 helpers ----
__device__ __forceinline__ u64 pack2(float a, float b) {
    u64 r; asm("mov.b64 %0, {%1, %2};" : "=l"(r) : "f"(a), "f"(b)); return r;
}
__device__ __forceinline__ void unpack2(u64 v, float& a, float& b) {
    asm("mov.b64 {%0, %1}, %2;" : "=f"(a), "=f"(b) : "l"(v));
}
__device__ __forceinline__ u64 fma2(u64 a, u64 b, u64 c) {
    u64 d; asm("fma.rn.f32x2 %0, %1, %2, %3;" : "=l"(d) : "l"(a), "l"(b), "l"(c)); return d;
}
__device__ __forceinline__ u64 relu2(u64 v) {
    float a, b; unpack2(v, a, b);
    return pack2(fmaxf(a, 0.f), fmaxf(b, 0.f));
}
__device__ __forceinline__ float sigm(float z) {
    float t; asm("tanh.approx.f32 %0, %1;" : "=f"(t) : "f"(z * 0.5f));
    return fmaf(t, 0.5f, 0.5f);
}
__device__ __forceinline__ void l2_prefetch(const void* p) {
    asm volatile("prefetch.global.L2 [%0];" :: "l"(p));
}

// params layout: w0[8][10]@0, w1[8][8]@80, w2[8]@144, b0[8]@152, b1[8]@160, b2@168

__global__ void __launch_bounds__(256)
dmh_kernel(const float* __restrict__ mask_feats,
           const float* __restrict__ params,
           const float* __restrict__ locs,
           const float* __restrict__ gt,
           const int*   __restrict__ im_inds,
           const int*   __restrict__ fpn_levels,
           float* __restrict__ out,
           float inv_n, int n_cta)
{
    extern __shared__ float smem[];
    float* Ls  = smem;                          // HW logits
    u64*   Wd  = (u64*)(smem + HW);             // 169 duplicated params {w,w}
    float* red = (float*)(Wd + NPARAM + 1);     // 24 floats reduction scratch

    const int inst = blockIdx.x;
    const int tid  = threadIdx.x;

    // ---- Phase A: load per-instance params, duplicated for packed math ----
    for (int i = tid; i < NPARAM; i += blockDim.x) {
        float w = params[inst * NPARAM + i];
        Wd[i] = pack2(w, w);
    }

    const int im  = im_inds[inst];
    const int lvl = fpn_levels[inst];
    const float soi_tab[5] = {8.f, 16.f, 32.f, 64.f, 128.f};
    const float inv_soi = 1.0f / soi_tab[lvl];
    const float lx = locs[inst * 2 + 0];
    const float ly = locs[inst * 2 + 1];
    const float* __restrict__ feat = mask_feats + (size_t)im * 8 * HW;
    const float* __restrict__ g = gt + (size_t)inst * OHW;   // 128B-aligned
    __syncthreads();

    // ---- Phase B: per-pixel 3-layer MLP with packed f32x2 FMA (4 px/thread) ----
    // Interleaved: L2-prefetch this CTA's gt slab (1700 x 128B) while computing.
    int it = 0;
    for (int p0 = tid * 4; p0 < HW; p0 += blockDim.x * 4, it++) {
        int line = it * 256 + tid;
        if (line < GT_LINES) l2_prefetch(g + line * 32);

        int y = p0 / Ww;
        int x = p0 - y * Ww;
        float cy  = (ly - (float)(y * 8 + 4)) * inv_soi;
        float cx0 = (lx - (float)(x * 8 + 4)) * inv_soi;
        float dx  = -8.f * inv_soi;

        u64 v2[10][2];
        v2[0][0] = pack2(cx0, cx0 + dx);
        v2[0][1] = pack2(cx0 + 2.f * dx, cx0 + 3.f * dx);
        v2[1][0] = pack2(cy, cy);
        v2[1][1] = v2[1][0];
        #pragma unroll
        for (int c = 0; c < 8; c++) {
            float4 f = *reinterpret_cast<const float4*>(feat + c * HW + p0);
            v2[2 + c][0] = pack2(f.x, f.y);
            v2[2 + c][1] = pack2(f.z, f.w);
        }

        u64 h0[8][2];
        #pragma unroll
        for (int c = 0; c < 8; c++) {
            u64 b  = Wd[152 + c];
            u64 a0 = b, a1 = b;
            #pragma unroll
            for (int i = 0; i < 10; i++) {
                u64 w = Wd[c * 10 + i];
                a0 = fma2(w, v2[i][0], a0);
                a1 = fma2(w, v2[i][1], a1);
            }
            h0[c][0] = relu2(a0);
            h0[c][1] = relu2(a1);
        }

        u64 h1[8][2];
        #pragma unroll
        for (int c = 0; c < 8; c++) {
            u64 b  = Wd[160 + c];
            u64 a0 = b, a1 = b;
            #pragma unroll
            for (int i = 0; i < 8; i++) {
                u64 w = Wd[80 + c * 8 + i];
                a0 = fma2(w, h0[i][0], a0);
                a1 = fma2(w, h0[i][1], a1);
            }
            h1[c][0] = relu2(a0);
            h1[c][1] = relu2(a1);
        }

        u64 zb = Wd[168];
        u64 z0 = zb, z1 = zb;
        #pragma unroll
        for (int i = 0; i < 8; i++) {
            u64 w = Wd[144 + i];
            z0 = fma2(w, h1[i][0], z0);
            z1 = fma2(w, h1[i][1], z1);
        }
        float o0, o1, o2, o3;
        unpack2(z0, o0, o1);
        unpack2(z1, o2, o3);
        *reinterpret_cast<float4*>(Ls + p0) = make_float4(o0, o1, o2, o3);
    }
    __syncthreads();

    // ---- Phase C: 16 px/thread, 4 batched LDG.128 (now mostly L2 hits) ----
    float inter = 0.f, ssum = 0.f, tsum = 0.f;
    const int NCHUNK = OHW / 16;   // 3400, OW = 17*16

    for (int ch = tid; ch < NCHUNK; ch += blockDim.x) {
        int y  = ch / 17;
        int xc = (ch - y * 17) * 16;
        int q0 = y * OW + xc;

        float4 t0 = *reinterpret_cast<const float4*>(g + q0);
        float4 t1 = *reinterpret_cast<const float4*>(g + q0 + 4);
        float4 t2 = *reinterpret_cast<const float4*>(g + q0 + 8);
        float4 t3 = *reinterpret_cast<const float4*>(g + q0 + 12);

        int jy  = max(y - 1, 0);
        int iy0 = jy >> 1;
        int iy1 = iy0 + (jy & 1);
        const float* r0 = Ls + iy0 * Ww;
        const float* r1 = Ls + iy1 * Ww;

        int c0 = xc >> 1;
        int cm = max(c0 - 1, 0);

        float4 A0 = *reinterpret_cast<const float4*>(r0 + c0);
        float4 B0 = *reinterpret_cast<const float4*>(r0 + c0 + 4);
        float4 A1 = *reinterpret_cast<const float4*>(r1 + c0);
        float4 B1 = *reinterpret_cast<const float4*>(r1 + c0 + 4);
        float  m0 = r0[cm];
        float  m1 = r1[cm];

        float Em = 0.5f * (m0 + m1);
        float E[8];
        E[0] = 0.5f * (A0.x + A1.x);
        E[1] = 0.5f * (A0.y + A1.y);
        E[2] = 0.5f * (A0.z + A1.z);
        E[3] = 0.5f * (A0.w + A1.w);
        E[4] = 0.5f * (B0.x + B1.x);
        E[5] = 0.5f * (B0.y + B1.y);
        E[6] = 0.5f * (B0.z + B1.z);
        E[7] = 0.5f * (B0.w + B1.w);

        float gtv[16] = {t0.x, t0.y, t0.z, t0.w, t1.x, t1.y, t1.z, t1.w,
                         t2.x, t2.y, t2.z, t2.w, t3.x, t3.y, t3.z, t3.w};
        #pragma unroll
        for (int j = 0; j < 4; j++) {
            float ep = (j == 0) ? Em : E[2 * j - 1];
            float e0 = E[2 * j];
            float e1 = E[2 * j + 1];
            float s0 = sigm(0.5f * (ep + e0));
            float s1 = sigm(e0);
            float s2 = sigm(0.5f * (e0 + e1));
            float s3 = sigm(e1);
            float g0 = gtv[4 * j + 0], g1 = gtv[4 * j + 1];
            float g2 = gtv[4 * j + 2], g3 = gtv[4 * j + 3];
            inter = fmaf(s0, g0, inter); ssum = fmaf(s0, s0, ssum); tsum = fmaf(g0, g0, tsum);
            inter = fmaf(s1, g1, inter); ssum = fmaf(s1, s1, ssum); tsum = fmaf(g1, g1, tsum);
            inter = fmaf(s2, g2, inter); ssum = fmaf(s2, s2, ssum); tsum = fmaf(g2, g2, tsum);
            inter = fmaf(s3, g3, inter); ssum = fmaf(s3, s3, ssum); tsum = fmaf(g3, g3, tsum);
        }
    }

    // ---- Phase D: block reduce, per-instance dice, last-CTA finalize ----
    #pragma unroll
    for (int off = 16; off > 0; off >>= 1) {
        inter += __shfl_down_sync(0xffffffffu, inter, off);
        ssum  += __shfl_down_sync(0xffffffffu, ssum,  off);
        tsum  += __shfl_down_sync(0xffffffffu, tsum,  off);
    }
    int warp = tid >> 5;
    if ((tid & 31) == 0) {
        red[warp]      = inter;
        red[8 + warp]  = ssum;
        red[16 + warp] = tsum;
    }
    __syncthreads();
    if (tid == 0) {
        float I = 0.f, S = 0.f, T = 0.f;
        #pragma unroll
        for (int w = 0; w < 8; w++) { I += red[w]; S += red[8 + w]; T += red[16 + w]; }
        float loss = 1.0f - 2.0f * I / (S + T + 1e-5f);

        atomicAdd(&g_sum, loss * inv_n);
        __threadfence();
        unsigned int ticket = atomicAdd(&g_count, 1u);
        if (ticket == (unsigned)(n_cta - 1)) {
            // all g_sum additions are ordered before their count increments;
            // an atomic RMW on g_sum now returns the final total.
            float tot = atomicAdd(&g_sum, 0.0f);
            out[0] = tot;
            g_sum   = 0.0f;      // reset for next graph replay
            g_count = 0u;
        }
    }
}

extern "C" void kernel_launch(void* const* d_in, const int* in_sizes, int n_in,
                              void* d_out, int out_size)
{
    const float* mask_feats = (const float*)d_in[0];
    const float* params     = (const float*)d_in[1];
    const float* locs       = (const float*)d_in[2];
    const float* gt         = (const float*)d_in[3];
    const int*   im_inds    = (const int*)d_in[4];
    const int*   fpn_levels = (const int*)d_in[5];
    float* out = (float*)d_out;

    int n_inst = in_sizes[1] / NPARAM;

    static int smem_set = 0;
    size_t smem_bytes = HW * sizeof(float) + (NPARAM + 1) * sizeof(u64) + 32 * sizeof(float);
    if (!smem_set) {
        cudaFuncSetAttribute(dmh_kernel, cudaFuncAttributeMaxDynamicSharedMemorySize,
                             (int)smem_bytes);
        smem_set = 1;
    }

    dmh_kernel<<<n_inst, 256, smem_bytes>>>(mask_feats, params, locs, gt,
                                            im_inds, fpn_levels, out,
                                            1.0f / (float)n_inst, n_inst);
}